// round 10
// baseline (speedup 1.0000x reference)
#include <cuda_runtime.h>
#include <cuda_fp16.h>

// Problem constants (fixed for this dataset)
#define BB   4
#define CC   128
#define HH   128
#define WW   128
#define GG   4
#define PP   9       // K*K taps
#define NOFF 72      // G*P*2
#define NMSK 36      // G*P
#define TILE 32      // pixels per block
#define NTHR 256
#define ROW  36      // xsT row length in floats (32 px + 4 pad, 16B-aligned)
#define SP   132     // padded scratch dim (img+pad); entry (b,g,yp,xp)

// fp16 pair-gather scratch: entry (b,g,yp,xp) = 128B =
//   [64B: ch0-31 of img col (xp-1), row (yp-1)] [64B: ch0-31 of img col xp]
// zero outside the image. 278784 entries * 128B = 35.7 MB.
#define NENT (BB * GG * SP * SP)
__device__ uint4 xh_scratch[NENT * 8];

// overlay buffer: phases 0/1 use it as xsT[CC][ROW] (18432 B);
// phases 2.5/3 use it as swt[TILE][NMSK] float4 (18432 B) + sent[TILE][NMSK] int
#define UBUF_BYTES (TILE * NMSK * 16 + TILE * NMSK * 4)   // 23040

// ---- packed f32x2 helpers (Blackwell FFMA2; fp32-exact) ----
__device__ __forceinline__ unsigned long long pk2(float lo, float hi) {
    unsigned long long r;
    asm("mov.b64 %0, {%1, %2};" : "=l"(r) : "f"(lo), "f"(hi));
    return r;
}
__device__ __forceinline__ void upk2(unsigned long long v, float& lo, float& hi) {
    asm("mov.b64 {%0, %1}, %2;" : "=f"(lo), "=f"(hi) : "l"(v));
}
__device__ __forceinline__ unsigned long long fma2(
    unsigned long long a, unsigned long long b, unsigned long long c) {
    unsigned long long d;
    asm("fma.rn.f32x2 %0, %1, %2, %3;" : "=l"(d) : "l"(a), "l"(b), "l"(c));
    return d;
}

// ---------------- conversion kernel: fp32 (B,H,W,C) -> fp16 pair scratch ----
__global__ __launch_bounds__(256) void conv_fp16(const float* __restrict__ in) {
    const int t = blockIdx.x * 256 + threadIdx.x;
    if (t >= NENT * 8) return;
    const int part = t & 7;          // 16B slice within the 128B entry
    const int e    = t >> 3;
    const int xp = e % SP;
    const int yp = (e / SP) % SP;
    const int g  = (e / (SP * SP)) % GG;
    const int b  =  e / (SP * SP * GG);
    const int col = xp - 1 + (part >> 2);   // part<4: left col, part>=4: right
    const int row = yp - 1;
    const int ch0 = (part & 3) * 8;
    uint4 v = make_uint4(0u, 0u, 0u, 0u);
    if ((unsigned)row < (unsigned)HH && (unsigned)col < (unsigned)WW) {
        const float4* s = reinterpret_cast<const float4*>(
            in + (((size_t)b * HH + row) * WW + col) * CC + g * 32 + ch0);
        const float4 f0 = s[0];
        const float4 f1 = s[1];
        __half2 h0 = __floats2half2_rn(f0.x, f0.y);
        __half2 h1 = __floats2half2_rn(f0.z, f0.w);
        __half2 h2 = __floats2half2_rn(f1.x, f1.y);
        __half2 h3 = __floats2half2_rn(f1.z, f1.w);
        v.x = *reinterpret_cast<unsigned int*>(&h0);
        v.y = *reinterpret_cast<unsigned int*>(&h1);
        v.z = *reinterpret_cast<unsigned int*>(&h2);
        v.w = *reinterpret_cast<unsigned int*>(&h3);
    }
    xh_scratch[t] = v;
}

// ---------------- main fused kernel ----------------------------------------
__global__ __launch_bounds__(NTHR, 5) void dcnv3_fused(
    const float* __restrict__ in,     // (B,H,W,C) channel-last
    const float* __restrict__ Woff,   // (C, 72) row-major
    const float* __restrict__ boff,   // (72)
    const float* __restrict__ Wmask,  // (C, 36) row-major
    const float* __restrict__ bmask,  // (36)
    float* __restrict__ out)          // (B,H,W,C) channel-last
{
    __shared__ __align__(16) char ubuf[UBUF_BYTES];   // 22.5 KB (xsT | swt+sent)
    __shared__ float offs[TILE][NOFF];                // 9 KB
    __shared__ float msk[TILE][NMSK];                 // 4.5 KB

    float* xsT           = reinterpret_cast<float*>(ubuf);             // [CC][ROW]
    float4 (*swt)[NMSK]  = reinterpret_cast<float4(*)[NMSK]>(ubuf);
    int (*sent)[NMSK]    = reinterpret_cast<int(*)[NMSK]>(ubuf + TILE * NMSK * 16);

    const int tid = threadIdx.x;
    const int blk = blockIdx.x;
    const int wt = blk % (WW / TILE);
    const int h  = (blk / (WW / TILE)) % HH;
    const int b  = blk / ((WW / TILE) * HH);
    const int w0 = wt * TILE;

    // ---- phase 0: load 32 pixels' features TRANSPOSED into xsT (fp32) ----
    const float4* xbase4 = reinterpret_cast<const float4*>(
        in + (((size_t)b * HH + h) * WW + w0) * CC);
    const int r = tid & 3;
    #pragma unroll
    for (int it = 0; it < 4; it++) {
        const int i  = tid + it * NTHR;      // 0..1023
        const int q  = i >> 7;               // pixel quad 0..7
        const int k4 = (i >> 2) & 31;        // channel quad 0..31
        float4 v = xbase4[(q * 4 + r) * (CC / 4) + k4];
        float a0 = v.x, a1 = v.y, a2 = v.z, a3 = v.w;
        {
            float s0 = (r & 1) ? a0 : a1;
            float s1 = (r & 1) ? a2 : a3;
            float g0 = __shfl_xor_sync(0xFFFFFFFF, s0, 1);
            float g1 = __shfl_xor_sync(0xFFFFFFFF, s1, 1);
            if (r & 1) { a0 = g0; a2 = g1; } else { a1 = g0; a3 = g1; }
        }
        {
            float u0 = (r & 2) ? a0 : a2;
            float u1 = (r & 2) ? a1 : a3;
            float h0 = __shfl_xor_sync(0xFFFFFFFF, u0, 2);
            float h1 = __shfl_xor_sync(0xFFFFFFFF, u1, 2);
            if (r & 2) { a0 = h0; a1 = h1; } else { a2 = h0; a3 = h1; }
        }
        *reinterpret_cast<float4*>(&xsT[(4 * k4 + r) * ROW + 4 * q]) =
            make_float4(a0, a1, a2, a3);
    }
    __syncthreads();

    // ---- phase 1: register-tiled matvec with packed f32x2 FMAs.
    // 4 pixels x 4 outputs per thread; pixel pairs packed into b64 lanes.
    if (tid < 216) {
        const int jq = tid >> 3;             // 0..26
        const int pg = tid & 7;              // 0..7
        const int p0 = pg * 4;
        const bool is_off = (jq < 18);
        const int j0 = is_off ? jq * 4 : (jq - 18) * 4;
        const float* Wb = (is_off ? Woff : Wmask) + j0;
        const int ws = is_off ? NOFF : NMSK;
        const float* bias = is_off ? boff : bmask;

        unsigned long long a01[4], a23[4];
        #pragma unroll
        for (int j = 0; j < 4; j++) { a01[j] = 0ULL; a23[j] = 0ULL; }

        #pragma unroll 4
        for (int k = 0; k < CC; k++) {
            const float4 xq = *reinterpret_cast<const float4*>(&xsT[k * ROW + p0]);
            const float4 w  = *reinterpret_cast<const float4*>(&Wb[k * ws]);
            const unsigned long long x01 = pk2(xq.x, xq.y);
            const unsigned long long x23 = pk2(xq.z, xq.w);
            const unsigned long long w0p = pk2(w.x, w.x);
            const unsigned long long w1p = pk2(w.y, w.y);
            const unsigned long long w2p = pk2(w.z, w.z);
            const unsigned long long w3p = pk2(w.w, w.w);
            a01[0] = fma2(x01, w0p, a01[0]);
            a23[0] = fma2(x23, w0p, a23[0]);
            a01[1] = fma2(x01, w1p, a01[1]);
            a23[1] = fma2(x23, w1p, a23[1]);
            a01[2] = fma2(x01, w2p, a01[2]);
            a23[2] = fma2(x23, w2p, a23[2]);
            a01[3] = fma2(x01, w3p, a01[3]);
            a23[3] = fma2(x23, w3p, a23[3]);
        }
        const float4 bv = *reinterpret_cast<const float4*>(bias + j0);
        const float bb[4] = { bv.x, bv.y, bv.z, bv.w };
        float ap[4][4];   // [pixel][output]
        #pragma unroll
        for (int j = 0; j < 4; j++) {
            float lo, hi;
            upk2(a01[j], lo, hi);
            ap[0][j] = lo + bb[j]; ap[1][j] = hi + bb[j];
            upk2(a23[j], lo, hi);
            ap[2][j] = lo + bb[j]; ap[3][j] = hi + bb[j];
        }
        #pragma unroll
        for (int p = 0; p < 4; p++) {
            const float4 res = make_float4(ap[p][0], ap[p][1], ap[p][2], ap[p][3]);
            if (is_off) *reinterpret_cast<float4*>(&offs[p0 + p][j0]) = res;
            else        *reinterpret_cast<float4*>(&msk[p0 + p][j0])  = res;
        }
    }
    __syncthreads();

    // ---- phase 2: softmax over the 9 taps per (pixel, group) ----
    if (tid < TILE * GG) {
        const int pp = tid / GG, g = tid % GG;
        float* m = &msk[pp][g * PP];
        float mx = m[0];
        #pragma unroll
        for (int p = 1; p < PP; p++) mx = fmaxf(mx, m[p]);
        float e[PP], s = 0.f;
        #pragma unroll
        for (int p = 0; p < PP; p++) { e[p] = __expf(m[p] - mx); s += e[p]; }
        const float inv = 1.f / s;
        #pragma unroll
        for (int p = 0; p < PP; p++) m[p] = e[p] * inv;
    }
    __syncthreads();

    // ---- phase 2.5: mask-folded corner weights + scratch ENTRY index ----
    // (overwrites xsT; safe — xsT dead after phase 1)
    for (int idx = tid; idx < TILE * NMSK; idx += NTHR) {
        const int pp = idx / NMSK;
        const int gp = idx % NMSK;
        const int g  = gp / PP;
        const int p  = gp % PP;
        const float dx = offs[pp][gp * 2 + 0];
        const float dy = offs[pp][gp * 2 + 1];
        const float px = (float)(w0 + pp) + (float)(p / 3) + dx;   // padded coords
        const float py = (float)h + (float)(p % 3) + dy;
        const float x0f = floorf(px), y0f = floorf(py);
        const float tx = px - x0f, ty = py - y0f;
        const int ix0 = (int)x0f, iy0 = (int)y0f;
        const float m = msk[pp][gp];

        float w00 = (1.f - tx) * (1.f - ty) * m;
        float w10 = tx * (1.f - ty) * m;
        float w01 = (1.f - tx) * ty * m;
        float w11 = tx * ty * m;
        // zero weights of out-of-range corners (img coord = padded-1)
        const bool vx0 = ((unsigned)(ix0 - 1) < (unsigned)WW);
        const bool vx1 = ((unsigned)(ix0)     < (unsigned)WW);
        const bool vy0 = ((unsigned)(iy0 - 1) < (unsigned)HH);
        const bool vy1 = ((unsigned)(iy0)     < (unsigned)HH);
        if (!(vx0 && vy0)) w00 = 0.f;
        if (!(vx1 && vy0)) w10 = 0.f;
        if (!(vx0 && vy1)) w01 = 0.f;
        if (!(vx1 && vy1)) w11 = 0.f;

        swt[pp][gp] = make_float4(w00, w10, w01, w11);
        // scratch entry (b,g, yp=iy0, xp=ix0); row+1 entry = +SP.  Clamp to 0
        // when the index would leave the padded array (weights all zero then).
        const bool ok = ((unsigned)ix0 <= 130u) && ((unsigned)iy0 <= 130u);
        sent[pp][gp] = ok ? (((b * GG + g) * SP + iy0) * SP + ix0) : 0;
    }
    __syncthreads();

    // ---- phase 3: fp16 pair gather with packed f32x2 accumulate.
    // warp = pixel; lane = (g, sub); sub>>2 = corner col half, sub&3 = ch octet.
    const int lane = tid & 31;
    const int g3   = lane >> 3;
    const int sub  = lane & 7;
    const int cr   = sub >> 2;          // 0: left corner col, 1: right

    #pragma unroll
    for (int pass = 0; pass < 4; pass++) {
        const int pp = (tid >> 5) + pass * 8;
        unsigned long long accP[4];
        #pragma unroll
        for (int i = 0; i < 4; i++) accP[i] = 0ULL;

        #pragma unroll
        for (int p = 0; p < PP; p++) {
            const int gp = g3 * PP + p;
            const float4 wv = swt[pp][gp];          // one LDS.128
            const float wr0 = cr ? wv.y : wv.x;     // row y0 weight for this col
            const float wr1 = cr ? wv.w : wv.z;     // row y1 weight
            const unsigned long long w0p = pk2(wr0, wr0);
            const unsigned long long w1p = pk2(wr1, wr1);
            const int e = sent[pp][gp];
            const uint4 d0 = xh_scratch[e * 8 + sub];
            const uint4 d1 = xh_scratch[(e + SP) * 8 + sub];
            float2 f;
            f = __half22float2(*reinterpret_cast<const __half2*>(&d0.x));
            accP[0] = fma2(pk2(f.x, f.y), w0p, accP[0]);
            f = __half22float2(*reinterpret_cast<const __half2*>(&d0.y));
            accP[1] = fma2(pk2(f.x, f.y), w0p, accP[1]);
            f = __half22float2(*reinterpret_cast<const __half2*>(&d0.z));
            accP[2] = fma2(pk2(f.x, f.y), w0p, accP[2]);
            f = __half22float2(*reinterpret_cast<const __half2*>(&d0.w));
            accP[3] = fma2(pk2(f.x, f.y), w0p, accP[3]);
            f = __half22float2(*reinterpret_cast<const __half2*>(&d1.x));
            accP[0] = fma2(pk2(f.x, f.y), w1p, accP[0]);
            f = __half22float2(*reinterpret_cast<const __half2*>(&d1.y));
            accP[1] = fma2(pk2(f.x, f.y), w1p, accP[1]);
            f = __half22float2(*reinterpret_cast<const __half2*>(&d1.z));
            accP[2] = fma2(pk2(f.x, f.y), w1p, accP[2]);
            f = __half22float2(*reinterpret_cast<const __half2*>(&d1.w));
            accP[3] = fma2(pk2(f.x, f.y), w1p, accP[3]);
        }
        float acc[8];
        #pragma unroll
        for (int i = 0; i < 4; i++) upk2(accP[i], acc[2 * i], acc[2 * i + 1]);
        // combine left/right corner partials (lane ^ 4)
        #pragma unroll
        for (int i = 0; i < 8; i++)
            acc[i] += __shfl_xor_sync(0xFFFFFFFF, acc[i], 4);

        if (!(lane & 4)) {      // sub in 0..3 -> channel octet
            float* op = out + (((size_t)b * HH + h) * WW + (w0 + pp)) * CC
                            + g3 * 32 + sub * 8;
            *reinterpret_cast<float4*>(op) =
                make_float4(acc[0], acc[1], acc[2], acc[3]);
            *reinterpret_cast<float4*>(op + 4) =
                make_float4(acc[4], acc[5], acc[6], acc[7]);
        }
    }
}

extern "C" void kernel_launch(void* const* d_in, const int* in_sizes, int n_in,
                              void* d_out, int out_size) {
    const float* inp   = (const float*)d_in[0];
    const float* Woff  = (const float*)d_in[1];
    const float* boff  = (const float*)d_in[2];
    const float* Wmask = (const float*)d_in[3];
    const float* bmask = (const float*)d_in[4];
    float* out = (float*)d_out;

    const int conv_blocks = (NENT * 8 + 255) / 256;     // 8712
    conv_fp16<<<conv_blocks, 256>>>(inp);

    const int nblocks = BB * HH * (WW / TILE);          // 2048
    dcnv3_fused<<<nblocks, NTHR>>>(inp, Woff, boff, Wmask, bmask, out);
}